// round 12
// baseline (speedup 1.0000x reference)
#include <cuda_runtime.h>
#include <cuda_bf16.h>
#include <cstdint>
#include <cstddef>

// ---------------------------------------------------------------------------
// LSTM: B=512, T=512, I=128, H=512, O=128. Gates [g,i,f,o].
// Persistent 128 CTAs. CTA (p,q): p = 128-row batch tile (4 groups),
// q = 16 h-cols x 4 gates = 64 N cols. Weights smem-resident.
// Round-12: chunk-granular inter-CTA barriers — h chunk kc is produced by
// q in [8kc,8kc+8); consumers poll per-chunk counters right before staging
// that chunk, absorbing straggler skew into the mma pipeline.
// ---------------------------------------------------------------------------

#define NCTA 128

__device__ __nv_bfloat16  g_wxtb[2048 * 128];            // Wx^T [n][k] bf16
__device__ __nv_bfloat16  g_wht[2048 * 512];             // Wh^T [n][k] bf16
__device__ __nv_bfloat16  g_xb[(size_t)512 * 512 * 128]; // x bf16 [b][t][i]
__device__ __nv_bfloat16  g_h[2][512 * 512];             // ping-pong h
__device__ float          g_hfinal[512 * 512];           // final h fp32
__device__ unsigned       g_barr[16 * 32];               // counter (p,kc) @ [(p*4+kc)*32]

// ---------------- PTX helpers ----------------------------------------------
__device__ __forceinline__ unsigned smem_u32(const void* p) {
    return (unsigned)__cvta_generic_to_shared(p);
}
__device__ __forceinline__ void cp16(void* dst_smem, const void* src) {
    asm volatile("cp.async.cg.shared.global [%0], [%1], 16;"
                 :: "r"(smem_u32(dst_smem)), "l"(src) : "memory");
}
__device__ __forceinline__ void cp_commit() {
    asm volatile("cp.async.commit_group;" ::: "memory");
}
template <int N>
__device__ __forceinline__ void cp_wait() {
    asm volatile("cp.async.wait_group %0;" :: "n"(N) : "memory");
}
__device__ __forceinline__ void ldm4(unsigned r[4], unsigned addr) {
    asm volatile("ldmatrix.sync.aligned.m8n8.x4.shared.b16 {%0,%1,%2,%3}, [%4];"
                 : "=r"(r[0]), "=r"(r[1]), "=r"(r[2]), "=r"(r[3]) : "r"(addr));
}
__device__ __forceinline__ void mma_bf16(float& d0, float& d1, float& d2, float& d3,
                                         unsigned a0, unsigned a1, unsigned a2, unsigned a3,
                                         unsigned b0, unsigned b1) {
    asm volatile(
        "mma.sync.aligned.m16n8k16.row.col.f32.bf16.bf16.f32 "
        "{%0,%1,%2,%3},{%4,%5,%6,%7},{%8,%9},{%0,%1,%2,%3};"
        : "+f"(d0), "+f"(d1), "+f"(d2), "+f"(d3)
        : "r"(a0), "r"(a1), "r"(a2), "r"(a3), "r"(b0), "r"(b1));
}
__device__ __forceinline__ float tanhfast(float x) {
    float y;
    asm("tanh.approx.f32 %0, %1;" : "=f"(y) : "f"(x));
    return y;
}
__device__ __forceinline__ float fsig(float x) {
    return fmaf(0.5f, tanhfast(0.5f * x), 0.5f);
}
__device__ __forceinline__ void barpair(int wm) {
    asm volatile("bar.sync %0, 64;" :: "r"(wm + 1) : "memory");
}
// poll a chunk counter until it reaches target, then acquire
__device__ __forceinline__ void poll_chunk(volatile unsigned* ctr, unsigned target) {
    if (*ctr < target) {
        while (*ctr < target) { }
    }
    __threadfence();
}

// ---- mma block: 8 k16 iterations via ldmatrix (layout proven round 10) ----
__device__ __forceinline__ void mma_block8(unsigned aAddr, unsigned bAddr,
                                           unsigned bPairStride, float acc[2][4][4]) {
#pragma unroll
    for (int k16 = 0; k16 < 8; k16++) {
        unsigned a[2][4], b01[4], b23[4];
        ldm4(a[0], aAddr + k16 * 32);
        ldm4(a[1], aAddr + 4352 + k16 * 32);
        ldm4(b01, bAddr + k16 * 32);
        ldm4(b23, bAddr + bPairStride + k16 * 32);
#pragma unroll
        for (int im = 0; im < 2; im++) {
            mma_bf16(acc[im][0][0], acc[im][0][1], acc[im][0][2], acc[im][0][3],
                     a[im][0], a[im][1], a[im][2], a[im][3], b01[0], b01[1]);
            mma_bf16(acc[im][1][0], acc[im][1][1], acc[im][1][2], acc[im][1][3],
                     a[im][0], a[im][1], a[im][2], a[im][3], b01[2], b01[3]);
            mma_bf16(acc[im][2][0], acc[im][2][1], acc[im][2][2], acc[im][2][3],
                     a[im][0], a[im][1], a[im][2], a[im][3], b23[0], b23[1]);
            mma_bf16(acc[im][3][0], acc[im][3][1], acc[im][3][2], acc[im][3][3],
                     a[im][0], a[im][1], a[im][2], a[im][3], b23[2], b23[3]);
        }
    }
}

// ---------------- converts ---------------------------------------------------
__global__ void conv_w(const float* __restrict__ Wx, const float* __restrict__ Wh) {
    int tid = blockIdx.x * blockDim.x + threadIdx.x;
    int stride = gridDim.x * blockDim.x;
    for (int o = tid; o < 2048 * 128; o += stride) {
        int k = o & 127, n = o >> 7;
        g_wxtb[o] = __float2bfloat16(Wx[(size_t)k * 2048 + n]);
    }
    for (int o = tid; o < 2048 * 512; o += stride) {
        int k = o & 511, n = o >> 9;
        g_wht[o] = __float2bfloat16(Wh[(size_t)k * 2048 + n]);
    }
}

__global__ void conv_x(const float* __restrict__ x) {
    const float4* x4 = (const float4*)x;
    size_t N4 = (size_t)512 * 512 * 128 / 4;
    for (size_t o = (size_t)blockIdx.x * blockDim.x + threadIdx.x; o < N4;
         o += (size_t)gridDim.x * blockDim.x) {
        float4 v = x4[o];
        __nv_bfloat162 lo = __floats2bfloat162_rn(v.x, v.y);
        __nv_bfloat162 hi = __floats2bfloat162_rn(v.z, v.w);
        uint2 pk;
        pk.x = *(unsigned*)&lo;
        pk.y = *(unsigned*)&hi;
        *(uint2*)(g_xb + o * 4) = pk;
    }
}

__global__ void reset_k() {
    int tid = blockIdx.x * blockDim.x + threadIdx.x;
    if (tid < 16 * 32) g_barr[tid] = 0u;
    for (int o = tid; o < 512 * 512; o += gridDim.x * blockDim.x)
        g_h[0][o] = __float2bfloat16(0.f);
}

// ---------------- persistent recurrence --------------------------------------
// smem layout (bytes):
//   Whs [64][520] bf16 : 0      .. 66560
//   Wxs [64][136] bf16 : 66560  .. 83968
//   As  3x[128][136] bf16 : 83968 .. 188416   (3 x 34816)
//   xs  [128][136] bf16 : 188416 .. 223232
#define AS_ELEMS (128 * 136)
#define AS_BYTES 34816
#define REC_SMEM 223232
__global__ void __launch_bounds__(256, 1) lstm_rec(const float* __restrict__ bias) {
    extern __shared__ char smem[];
    __nv_bfloat16* Whs = (__nv_bfloat16*)smem;
    __nv_bfloat16* Wxs = (__nv_bfloat16*)(smem + 66560);
    __nv_bfloat16* As0 = (__nv_bfloat16*)(smem + 83968);
    __nv_bfloat16* xs  = (__nv_bfloat16*)(smem + 188416);

    const int tid = threadIdx.x;
    const int lane = tid & 31, warp = tid >> 5;
    const int wm = warp & 3, wn = warp >> 2;
    const int q = blockIdx.x & 31, p = blockIdx.x >> 5;
    const int tr = lane >> 2, tc = (lane & 3) * 2;
    const int rbase = p * 128;
    const int pairrow = wm * 32 + wn * 16;   // this warp's 16-row staging slice

    // per-chunk counters: consumer polls barc[kc]; producer arrives at own chunk
    volatile unsigned* barc[4];
#pragma unroll
    for (int kc = 0; kc < 4; kc++)
        barc[kc] = (volatile unsigned*)&g_barr[(p * 4 + kc) << 5];
    unsigned* mybar = &g_barr[(p * 4 + (q >> 3)) << 5];

    // ---- per-thread ldmatrix addresses (verified in round 10) ----
    const unsigned aoff =
        (unsigned)(wm * 32 + (lane & 7) + ((lane >> 3) & 1) * 8) * 272u +
        (unsigned)((lane >> 4) & 1) * 16u;
    const unsigned bRowWh =
        (unsigned)(((lane >> 4) & 1) * 16 + wn * 8 + (lane & 7));
    const unsigned bColSel = (unsigned)((lane >> 3) & 1) * 16u;
    const unsigned sWh = smem_u32(Whs) + bRowWh * 1040u + bColSel;   // + kc*256
    const unsigned sWx = smem_u32(Wxs) + bRowWh * 272u + bColSel;
    const unsigned sX  = smem_u32(xs) + aoff;
    unsigned sA[3];
    sA[0] = smem_u32(As0) + aoff;
    sA[1] = sA[0] + AS_BYTES;
    sA[2] = sA[0] + 2 * AS_BYTES;
    const unsigned WH_PAIR = 32u * 1040u;
    const unsigned WX_PAIR = 32u * 272u;

    // ---- prologue (CTA-wide syncs allowed here) ----
    for (int i = tid; i < 4096; i += 256) {
        int rowi = i >> 6, ch = i & 63;
        int gate = rowi >> 4, lc = rowi & 15;
        cp16(&Whs[rowi * 520 + ch * 8],
             g_wht + (size_t)(gate * 512 + q * 16 + lc) * 512 + ch * 8);
    }
    for (int i = tid; i < 1024; i += 256) {
        int rowi = i >> 4, ch = i & 15;
        int gate = rowi >> 4, lc = rowi & 15;
        cp16(&Wxs[rowi * 136 + ch * 8],
             g_wxtb + (size_t)(gate * 512 + q * 16 + lc) * 128 + ch * 8);
    }
    for (int i = tid; i < 2048; i += 256) {
        int r = i >> 4, ch = i & 15;
        cp16(&xs[r * 136 + ch * 8],
             g_xb + ((size_t)(rbase + r) * 512 + 0) * 128 + ch * 8);
    }
    cp_commit(); cp_wait<0>(); __syncthreads();

    float bz[4][2];
    {
        int col = q * 16 + wn * 8 + tc;
#pragma unroll
        for (int g = 0; g < 4; g++) {
            bz[g][0] = bias[g * 512 + col];
            bz[g][1] = bias[g * 512 + col + 1];
        }
    }

    float c[2][4];
#pragma unroll
    for (int im = 0; im < 2; im++)
#pragma unroll
        for (int e = 0; e < 4; e++) c[im][e] = 0.f;

    // acc for step 0: bias + x(0)@Wx
    float acc[2][4][4];
#pragma unroll
    for (int im = 0; im < 2; im++)
#pragma unroll
        for (int g = 0; g < 4; g++) {
            acc[im][g][0] = bz[g][0]; acc[im][g][1] = bz[g][1];
            acc[im][g][2] = bz[g][0]; acc[im][g][3] = bz[g][1];
        }
    mma_block8(sX, sWx, WX_PAIR, acc);
    __syncthreads();   // last CTA-wide sync; steady loop is warp/pair-local

    for (int t = 0; t < 512; ++t) {
        const int cur = t & 1, nxt = cur ^ 1;
        const __nv_bfloat16* hsrc = g_h[cur] + (size_t)(rbase + pairrow) * 512;
        const unsigned tgt = (unsigned)t * 64u;   // h(t) writers have arrived

        // stage h chunk 0 -> buf0, chunk 1 -> buf1 (poll each chunk's producers)
        poll_chunk(barc[0], tgt);
        for (int i = lane; i < 256; i += 32) {
            int r = i >> 4, ch = i & 15;
            cp16(As0 + (pairrow + r) * 136 + ch * 8,
                 hsrc + (size_t)r * 512 + 0 * 128 + ch * 8);
        }
        cp_commit();
        poll_chunk(barc[1], tgt);
        for (int i = lane; i < 256; i += 32) {
            int r = i >> 4, ch = i & 15;
            cp16(As0 + AS_ELEMS + (pairrow + r) * 136 + ch * 8,
                 hsrc + (size_t)r * 512 + 1 * 128 + ch * 8);
        }
        cp_commit();
        // pending {h0,h1}

        // kc=0: h0 ready; stage h2 -> buf2
        cp_wait<1>(); barpair(wm);
        poll_chunk(barc[2], tgt);
        for (int i = lane; i < 256; i += 32) {
            int r = i >> 4, ch = i & 15;
            cp16(As0 + 2 * AS_ELEMS + (pairrow + r) * 136 + ch * 8,
                 hsrc + (size_t)r * 512 + 2 * 128 + ch * 8);
        }
        cp_commit();   // {h1,h2}
        mma_block8(sA[0], sWh, WH_PAIR, acc);

        // kc=1: h1 ready; stage h3 -> buf0
        cp_wait<1>(); barpair(wm);
        poll_chunk(barc[3], tgt);
        for (int i = lane; i < 256; i += 32) {
            int r = i >> 4, ch = i & 15;
            cp16(As0 + (pairrow + r) * 136 + ch * 8,
                 hsrc + (size_t)r * 512 + 3 * 128 + ch * 8);
        }
        cp_commit();   // {h2,h3}
        mma_block8(sA[1], sWh + 256, WH_PAIR, acc);

        // kc=2: h2 ready; prefetch x(t+1) slice
        cp_wait<1>(); barpair(wm);
        if (t < 511) {
            for (int i = lane; i < 256; i += 32) {
                int r = i >> 4, ch = i & 15;
                cp16(xs + (pairrow + r) * 136 + ch * 8,
                     g_xb + ((size_t)(rbase + pairrow + r) * 512 + (t + 1)) * 128 + ch * 8);
            }
            cp_commit();   // {h3,x'}
        }
        mma_block8(sA[2], sWh + 512, WH_PAIR, acc);

        // kc=3: h3 ready
        if (t < 511) cp_wait<1>(); else cp_wait<0>();
        barpair(wm);
        mma_block8(sA[0], sWh + 768, WH_PAIR, acc);

        // ---- gates + state update + h writeback (MUFU.TANH) ----
#pragma unroll
        for (int im = 0; im < 2; im++) {
            int grow = rbase + wm * 32 + im * 16 + tr;
            int hcol = q * 16 + wn * 8 + tc;
            float hv[4];
#pragma unroll
            for (int e = 0; e < 4; e++) {
                float gv = tanhfast(acc[im][0][e]);
                float iv = fsig(acc[im][1][e]);
                float fv = fsig(acc[im][2][e]);
                float ov = fsig(acc[im][3][e]);
                float cc2 = gv * iv + c[im][e] * fv;
                c[im][e] = cc2;
                hv[e] = tanhfast(cc2) * ov;
            }
            if (t < 511) {
                *(__nv_bfloat162*)(g_h[nxt] + (size_t)grow * 512 + hcol) =
                    __floats2bfloat162_rn(hv[0], hv[1]);
                *(__nv_bfloat162*)(g_h[nxt] + (size_t)(grow + 8) * 512 + hcol) =
                    __floats2bfloat162_rn(hv[2], hv[3]);
            } else {
                *(float2*)(g_hfinal + (size_t)grow * 512 + hcol) = make_float2(hv[0], hv[1]);
                *(float2*)(g_hfinal + (size_t)(grow + 8) * 512 + hcol) = make_float2(hv[2], hv[3]);
            }
        }

        if (t == 511) break;

        // ---- arrive at this CTA's chunk counter (warp-granular, 64/step) ----
        __syncwarp();
        if (lane == 0) {
            __threadfence();
            atomicAdd(mybar, 1u);
        }

        // ---- barrier shadow: x-GEMM for t+1 ----
        cp_wait<0>();      // x' slice complete
        barpair(wm);       // sibling's x' slice visible too
#pragma unroll
        for (int im = 0; im < 2; im++)
#pragma unroll
            for (int g = 0; g < 4; g++) {
                acc[im][g][0] = bz[g][0]; acc[im][g][1] = bz[g][1];
                acc[im][g][2] = bz[g][0]; acc[im][g][3] = bz[g][1];
            }
        mma_block8(sX, sWx, WX_PAIR, acc);
        // next step's chunk polls happen at loop top
    }
}

// ---------------- projection + softmax ---------------------------------------
__global__ void proj_kernel(const float* __restrict__ Wp, const float* __restrict__ bp,
                            float* __restrict__ out) {
    __shared__ float hs[512];
    __shared__ float wred[8];
    int b = blockIdx.x, o = threadIdx.x;
    for (int i = o; i < 512; i += 128)
        hs[i] = fminf(fmaxf(g_hfinal[(size_t)b * 512 + i], -1.f), 1.f);
    __syncthreads();
    float acc = bp[o];
#pragma unroll 8
    for (int k = 0; k < 512; k++) acc = fmaf(hs[k], Wp[(size_t)k * 128 + o], acc);
    float m = acc;
#pragma unroll
    for (int s = 16; s > 0; s >>= 1) m = fmaxf(m, __shfl_xor_sync(0xffffffffu, m, s));
    int w = o >> 5, ln = o & 31;
    if (ln == 0) wred[w] = m;
    __syncthreads();
    m = fmaxf(fmaxf(wred[0], wred[1]), fmaxf(wred[2], wred[3]));
    float e = __expf(acc - m);
    float s = e;
#pragma unroll
    for (int sh = 16; sh > 0; sh >>= 1) s += __shfl_xor_sync(0xffffffffu, s, sh);
    if (ln == 0) wred[4 + w] = s;
    __syncthreads();
    s = wred[4] + wred[5] + wred[6] + wred[7];
    out[(size_t)b * 128 + o] = e * __fdividef(1.f, s);
}

// ---------------- launch ------------------------------------------------------
// Inputs resolved BY ELEMENT COUNT (all six sizes distinct):
//   x: 33554432, Wx: 262144, Wh: 1048576, b: 2048, Wp: 65536, bp: 128
extern "C" void kernel_launch(void* const* d_in, const int* in_sizes, int n_in,
                              void* d_out, int out_size) {
    (void)out_size;
    const float *x = 0, *Wx = 0, *Wh = 0, *b = 0, *Wp = 0, *bp = 0;
    for (int i = 0; i < n_in; i++) {
        switch (in_sizes[i]) {
            case 512 * 512 * 128: x  = (const float*)d_in[i]; break;
            case 128 * 2048:      Wx = (const float*)d_in[i]; break;
            case 512 * 2048:      Wh = (const float*)d_in[i]; break;
            case 2048:            b  = (const float*)d_in[i]; break;
            case 512 * 128:       Wp = (const float*)d_in[i]; break;
            case 128:             bp = (const float*)d_in[i]; break;
            default: break;
        }
    }
    float* out = (float*)d_out;

    cudaFuncSetAttribute(lstm_rec, cudaFuncAttributeMaxDynamicSharedMemorySize, REC_SMEM);

    conv_w<<<512, 256>>>(Wx, Wh);
    conv_x<<<512, 256>>>(x);
    reset_k<<<128, 256>>>();
    lstm_rec<<<NCTA, 256, REC_SMEM>>>(b);
    proj_kernel<<<512, 128>>>(Wp, bp, out);
}

// round 13
// speedup vs baseline: 1.3340x; 1.3340x over previous
#include <cuda_runtime.h>
#include <cuda_bf16.h>
#include <cstdint>
#include <cstddef>

// ---------------------------------------------------------------------------
// LSTM: B=512, T=512, I=128, H=512, O=128. Gates [g,i,f,o].
// Persistent 128 CTAs, 384 threads: warps 0-7 consumers (mma+gates),
// warps 8-11 producers (poll + cp.async staging). Named-barrier handshake.
// CTA (p,q): p = 128-row batch tile, q = 16 h-cols x 4 gates = 64 N cols.
// ---------------------------------------------------------------------------

#define NCTA 128

__device__ __nv_bfloat16  g_wxtb[2048 * 128];            // Wx^T [n][k] bf16
__device__ __nv_bfloat16  g_wht[2048 * 512];             // Wh^T [n][k] bf16
__device__ __nv_bfloat16  g_xb[(size_t)512 * 512 * 128]; // x bf16 [b][t][i]
__device__ __nv_bfloat16  g_h[2][512 * 512];             // ping-pong h
__device__ float          g_hfinal[512 * 512];           // final h fp32
__device__ unsigned       g_barr[32 * 32];               // per-p counters @ [p*32]

// named barrier ids (0 reserved for __syncthreads)
#define RDY0 1
#define RDY1 2
#define RDY2 3
#define FRE0 4
#define FRE1 5
#define FRE2 6
#define RDYX 7
#define FREX 8

// ---------------- PTX helpers ----------------------------------------------
__device__ __forceinline__ unsigned smem_u32(const void* p) {
    return (unsigned)__cvta_generic_to_shared(p);
}
__device__ __forceinline__ void cp16(void* dst_smem, const void* src) {
    asm volatile("cp.async.cg.shared.global [%0], [%1], 16;"
                 :: "r"(smem_u32(dst_smem)), "l"(src) : "memory");
}
__device__ __forceinline__ void cp_commit() {
    asm volatile("cp.async.commit_group;" ::: "memory");
}
template <int N>
__device__ __forceinline__ void cp_wait() {
    asm volatile("cp.async.wait_group %0;" :: "n"(N) : "memory");
}
__device__ __forceinline__ void bsync(int id) {
    asm volatile("bar.sync %0, 384;" :: "r"(id) : "memory");
}
__device__ __forceinline__ void barrive(int id) {
    asm volatile("bar.arrive %0, 384;" :: "r"(id) : "memory");
}
__device__ __forceinline__ void ldm4(unsigned r[4], unsigned addr) {
    asm volatile("ldmatrix.sync.aligned.m8n8.x4.shared.b16 {%0,%1,%2,%3}, [%4];"
                 : "=r"(r[0]), "=r"(r[1]), "=r"(r[2]), "=r"(r[3]) : "r"(addr));
}
__device__ __forceinline__ void mma_bf16(float& d0, float& d1, float& d2, float& d3,
                                         unsigned a0, unsigned a1, unsigned a2, unsigned a3,
                                         unsigned b0, unsigned b1) {
    asm volatile(
        "mma.sync.aligned.m16n8k16.row.col.f32.bf16.bf16.f32 "
        "{%0,%1,%2,%3},{%4,%5,%6,%7},{%8,%9},{%0,%1,%2,%3};"
        : "+f"(d0), "+f"(d1), "+f"(d2), "+f"(d3)
        : "r"(a0), "r"(a1), "r"(a2), "r"(a3), "r"(b0), "r"(b1));
}
__device__ __forceinline__ float tanhfast(float x) {
    float y;
    asm("tanh.approx.f32 %0, %1;" : "=f"(y) : "f"(x));
    return y;
}
__device__ __forceinline__ float fsig(float x) {
    return fmaf(0.5f, tanhfast(0.5f * x), 0.5f);
}

// ---- mma block: 8 k16 iterations via ldmatrix (layout proven rounds 10-12) ----
__device__ __forceinline__ void mma_block8(unsigned aAddr, unsigned bAddr,
                                           unsigned bPairStride, float acc[2][4][4]) {
#pragma unroll
    for (int k16 = 0; k16 < 8; k16++) {
        unsigned a[2][4], b01[4], b23[4];
        ldm4(a[0], aAddr + k16 * 32);
        ldm4(a[1], aAddr + 4352 + k16 * 32);
        ldm4(b01, bAddr + k16 * 32);
        ldm4(b23, bAddr + bPairStride + k16 * 32);
#pragma unroll
        for (int im = 0; im < 2; im++) {
            mma_bf16(acc[im][0][0], acc[im][0][1], acc[im][0][2], acc[im][0][3],
                     a[im][0], a[im][1], a[im][2], a[im][3], b01[0], b01[1]);
            mma_bf16(acc[im][1][0], acc[im][1][1], acc[im][1][2], acc[im][1][3],
                     a[im][0], a[im][1], a[im][2], a[im][3], b01[2], b01[3]);
            mma_bf16(acc[im][2][0], acc[im][2][1], acc[im][2][2], acc[im][2][3],
                     a[im][0], a[im][1], a[im][2], a[im][3], b23[0], b23[1]);
            mma_bf16(acc[im][3][0], acc[im][3][1], acc[im][3][2], acc[im][3][3],
                     a[im][0], a[im][1], a[im][2], a[im][3], b23[2], b23[3]);
        }
    }
}

// ---------------- converts ---------------------------------------------------
__global__ void conv_w(const float* __restrict__ Wx, const float* __restrict__ Wh) {
    int tid = blockIdx.x * blockDim.x + threadIdx.x;
    int stride = gridDim.x * blockDim.x;
    for (int o = tid; o < 2048 * 128; o += stride) {
        int k = o & 127, n = o >> 7;
        g_wxtb[o] = __float2bfloat16(Wx[(size_t)k * 2048 + n]);
    }
    for (int o = tid; o < 2048 * 512; o += stride) {
        int k = o & 511, n = o >> 9;
        g_wht[o] = __float2bfloat16(Wh[(size_t)k * 2048 + n]);
    }
}

__global__ void conv_x(const float* __restrict__ x) {
    const float4* x4 = (const float4*)x;
    size_t N4 = (size_t)512 * 512 * 128 / 4;
    for (size_t o = (size_t)blockIdx.x * blockDim.x + threadIdx.x; o < N4;
         o += (size_t)gridDim.x * blockDim.x) {
        float4 v = x4[o];
        __nv_bfloat162 lo = __floats2bfloat162_rn(v.x, v.y);
        __nv_bfloat162 hi = __floats2bfloat162_rn(v.z, v.w);
        uint2 pk;
        pk.x = *(unsigned*)&lo;
        pk.y = *(unsigned*)&hi;
        *(uint2*)(g_xb + o * 4) = pk;
    }
}

__global__ void reset_k() {
    int tid = blockIdx.x * blockDim.x + threadIdx.x;
    if (tid < 32 * 32) g_barr[tid] = 0u;
    for (int o = tid; o < 512 * 512; o += gridDim.x * blockDim.x)
        g_h[0][o] = __float2bfloat16(0.f);
}

// ---------------- persistent recurrence --------------------------------------
// smem layout (bytes):
//   Whs [64][520] bf16 : 0      .. 66560
//   Wxs [64][136] bf16 : 66560  .. 83968
//   As  3x[128][136] bf16 : 83968 .. 188416   (3 x 34816)
//   xs  [128][136] bf16 : 188416 .. 223232
#define AS_ELEMS (128 * 136)
#define AS_BYTES 34816
#define REC_SMEM 223232
__global__ void __launch_bounds__(384, 1) lstm_rec(const float* __restrict__ bias) {
    extern __shared__ char smem[];
    __nv_bfloat16* Whs = (__nv_bfloat16*)smem;
    __nv_bfloat16* Wxs = (__nv_bfloat16*)(smem + 66560);
    __nv_bfloat16* As0 = (__nv_bfloat16*)(smem + 83968);
    __nv_bfloat16* xs  = (__nv_bfloat16*)(smem + 188416);

    const int tid = threadIdx.x;
    const int lane = tid & 31, warp = tid >> 5;
    const int q = blockIdx.x & 31, p = blockIdx.x >> 5;
    const int rbase = p * 128;
    volatile unsigned* barp = (volatile unsigned*)&g_barr[p << 5];

    // ---- prologue: stage Wh, Wx, x(0) with all 384 threads ----
    for (int i = tid; i < 4096; i += 384) {
        int rowi = i >> 6, ch = i & 63;
        int gate = rowi >> 4, lc = rowi & 15;
        cp16(&Whs[rowi * 520 + ch * 8],
             g_wht + (size_t)(gate * 512 + q * 16 + lc) * 512 + ch * 8);
    }
    for (int i = tid; i < 1024; i += 384) {
        int rowi = i >> 4, ch = i & 15;
        int gate = rowi >> 4, lc = rowi & 15;
        cp16(&Wxs[rowi * 136 + ch * 8],
             g_wxtb + (size_t)(gate * 512 + q * 16 + lc) * 128 + ch * 8);
    }
    for (int i = tid; i < 2048; i += 384) {
        int r = i >> 4, ch = i & 15;
        cp16(&xs[r * 136 + ch * 8],
             g_xb + ((size_t)(rbase + r) * 512 + 0) * 128 + ch * 8);
    }
    cp_commit(); cp_wait<0>(); __syncthreads();

    if (warp < 8) {
        // =================== CONSUMER (warps 0-7) ===================
        const int wm = warp & 3, wn = warp >> 2;
        const int tr = lane >> 2, tc = (lane & 3) * 2;

        // ldmatrix addresses (verified rounds 10-12)
        const unsigned aoff =
            (unsigned)(wm * 32 + (lane & 7) + ((lane >> 3) & 1) * 8) * 272u +
            (unsigned)((lane >> 4) & 1) * 16u;
        const unsigned bRowWh =
            (unsigned)(((lane >> 4) & 1) * 16 + wn * 8 + (lane & 7));
        const unsigned bColSel = (unsigned)((lane >> 3) & 1) * 16u;
        const unsigned sWh = smem_u32(Whs) + bRowWh * 1040u + bColSel;
        const unsigned sWx = smem_u32(Wxs) + bRowWh * 272u + bColSel;
        const unsigned sX  = smem_u32(xs) + aoff;
        unsigned sA[3];
        sA[0] = smem_u32(As0) + aoff;
        sA[1] = sA[0] + AS_BYTES;
        sA[2] = sA[0] + 2 * AS_BYTES;
        const unsigned WH_PAIR = 32u * 1040u;
        const unsigned WX_PAIR = 32u * 272u;

        float bz[4][2];
        {
            int col = q * 16 + wn * 8 + tc;
#pragma unroll
            for (int g = 0; g < 4; g++) {
                bz[g][0] = bias[g * 512 + col];
                bz[g][1] = bias[g * 512 + col + 1];
            }
        }
        float c[2][4];
#pragma unroll
        for (int im = 0; im < 2; im++)
#pragma unroll
            for (int e = 0; e < 4; e++) c[im][e] = 0.f;

        // pre-arm the free barriers (producers sync them at t=0)
        barrive(FRE0); barrive(FRE1); barrive(FRE2);

        for (int t = 0; t < 512; ++t) {
            // x-GEMM for this step (xs(t) staged by prologue / producers)
            if (t > 0) bsync(RDYX);
            float acc[2][4][4];
#pragma unroll
            for (int im = 0; im < 2; im++)
#pragma unroll
                for (int g = 0; g < 4; g++) {
                    acc[im][g][0] = bz[g][0]; acc[im][g][1] = bz[g][1];
                    acc[im][g][2] = bz[g][0]; acc[im][g][3] = bz[g][1];
                }
            mma_block8(sX, sWx, WX_PAIR, acc);
            if (t < 511) barrive(FREX);

            // h-GEMM: 4 chunks through the 3-buffer ring
            bsync(RDY0); mma_block8(sA[0], sWh,       WH_PAIR, acc); barrive(FRE0);
            bsync(RDY1); mma_block8(sA[1], sWh + 256, WH_PAIR, acc); barrive(FRE1);
            bsync(RDY2); mma_block8(sA[2], sWh + 512, WH_PAIR, acc); barrive(FRE2);
            bsync(RDY0); mma_block8(sA[0], sWh + 768, WH_PAIR, acc); barrive(FRE0);

            // gates + state update + h writeback
#pragma unroll
            for (int im = 0; im < 2; im++) {
                int grow = rbase + wm * 32 + im * 16 + tr;
                int hcol = q * 16 + wn * 8 + tc;
                float hv[4];
#pragma unroll
                for (int e = 0; e < 4; e++) {
                    float gv = tanhfast(acc[im][0][e]);
                    float iv = fsig(acc[im][1][e]);
                    float fv = fsig(acc[im][2][e]);
                    float ov = fsig(acc[im][3][e]);
                    float cc2 = gv * iv + c[im][e] * fv;
                    c[im][e] = cc2;
                    hv[e] = tanhfast(cc2) * ov;
                }
                if (t < 511) {
                    *(__nv_bfloat162*)(g_h[(t + 1) & 1] + (size_t)grow * 512 + hcol) =
                        __floats2bfloat162_rn(hv[0], hv[1]);
                    *(__nv_bfloat162*)(g_h[(t + 1) & 1] + (size_t)(grow + 8) * 512 + hcol) =
                        __floats2bfloat162_rn(hv[2], hv[3]);
                } else {
                    *(float2*)(g_hfinal + (size_t)grow * 512 + hcol) = make_float2(hv[0], hv[1]);
                    *(float2*)(g_hfinal + (size_t)(grow + 8) * 512 + hcol) = make_float2(hv[2], hv[3]);
                }
            }

            // arrive at the inter-CTA counter (8 consumer warps x 32 CTAs = 256)
            if (t < 511) {
                __syncwarp();
                if (lane == 0) {
                    __threadfence();
                    atomicAdd((unsigned*)barp, 1u);
                }
            }
        }
    } else {
        // =================== PRODUCER (warps 8-11) ===================
        const int pw = warp - 8;           // 0..3 -> rows [pw*32, pw*32+32)
        for (int t = 0; t < 512; ++t) {
            // wait for h(t) producers chip-wide (256 consumer-warp arrivals/step)
            unsigned tgt = (unsigned)t * 256u;
            while (*barp < tgt) { }
            __threadfence();

            const __nv_bfloat16* hsrc = g_h[t & 1] + (size_t)rbase * 512;

            // chunk0 -> buf0
            bsync(FRE0);
            for (int i = lane; i < 512; i += 32) {
                int r = pw * 32 + (i >> 4), ch = i & 15;
                cp16(As0 + r * 136 + ch * 8, hsrc + (size_t)r * 512 + 0 * 128 + ch * 8);
            }
            cp_commit();
            // chunk1 -> buf1
            bsync(FRE1);
            for (int i = lane; i < 512; i += 32) {
                int r = pw * 32 + (i >> 4), ch = i & 15;
                cp16(As0 + AS_ELEMS + r * 136 + ch * 8, hsrc + (size_t)r * 512 + 1 * 128 + ch * 8);
            }
            cp_commit();
            // chunk2 -> buf2
            bsync(FRE2);
            for (int i = lane; i < 512; i += 32) {
                int r = pw * 32 + (i >> 4), ch = i & 15;
                cp16(As0 + 2 * AS_ELEMS + r * 136 + ch * 8, hsrc + (size_t)r * 512 + 2 * 128 + ch * 8);
            }
            cp_commit();
            cp_wait<2>();          // chunk0 complete
            barrive(RDY0);
            // chunk3 -> buf0 (after consumers free it post chunk0-mma)
            bsync(FRE0);
            for (int i = lane; i < 512; i += 32) {
                int r = pw * 32 + (i >> 4), ch = i & 15;
                cp16(As0 + r * 136 + ch * 8, hsrc + (size_t)r * 512 + 3 * 128 + ch * 8);
            }
            cp_commit();
            cp_wait<2>();          // chunk1 complete
            barrive(RDY1);
            if (t < 511) {
                // xs(t+1) after consumers finish x_mma(t)
                bsync(FREX);
                for (int i = lane; i < 512; i += 32) {
                    int r = pw * 32 + (i >> 4), ch = i & 15;
                    cp16(xs + r * 136 + ch * 8,
                         g_xb + ((size_t)(rbase + r) * 512 + (t + 1)) * 128 + ch * 8);
                }
                cp_commit();
                cp_wait<2>();      // chunk2 complete
                barrive(RDY2);
                cp_wait<1>();      // chunk3 complete
                barrive(RDY0);
                cp_wait<0>();      // xs complete
                barrive(RDYX);
            } else {
                cp_wait<1>();      // chunk2 complete
                barrive(RDY2);
                cp_wait<0>();      // chunk3 complete
                barrive(RDY0);
            }
        }
    }
}

// ---------------- projection + softmax ---------------------------------------
__global__ void proj_kernel(const float* __restrict__ Wp, const float* __restrict__ bp,
                            float* __restrict__ out) {
    __shared__ float hs[512];
    __shared__ float wred[8];
    int b = blockIdx.x, o = threadIdx.x;
    for (int i = o; i < 512; i += 128)
        hs[i] = fminf(fmaxf(g_hfinal[(size_t)b * 512 + i], -1.f), 1.f);
    __syncthreads();
    float acc = bp[o];
#pragma unroll 8
    for (int k = 0; k < 512; k++) acc = fmaf(hs[k], Wp[(size_t)k * 128 + o], acc);
    float m = acc;
#pragma unroll
    for (int s = 16; s > 0; s >>= 1) m = fmaxf(m, __shfl_xor_sync(0xffffffffu, m, s));
    int w = o >> 5, ln = o & 31;
    if (ln == 0) wred[w] = m;
    __syncthreads();
    m = fmaxf(fmaxf(wred[0], wred[1]), fmaxf(wred[2], wred[3]));
    float e = __expf(acc - m);
    float s = e;
#pragma unroll
    for (int sh = 16; sh > 0; sh >>= 1) s += __shfl_xor_sync(0xffffffffu, s, sh);
    if (ln == 0) wred[4 + w] = s;
    __syncthreads();
    s = wred[4] + wred[5] + wred[6] + wred[7];
    out[(size_t)b * 128 + o] = e * __fdividef(1.f, s);
}

// ---------------- launch ------------------------------------------------------
// Inputs resolved BY ELEMENT COUNT (all six sizes distinct):
//   x: 33554432, Wx: 262144, Wh: 1048576, b: 2048, Wp: 65536, bp: 128
extern "C" void kernel_launch(void* const* d_in, const int* in_sizes, int n_in,
                              void* d_out, int out_size) {
    (void)out_size;
    const float *x = 0, *Wx = 0, *Wh = 0, *b = 0, *Wp = 0, *bp = 0;
    for (int i = 0; i < n_in; i++) {
        switch (in_sizes[i]) {
            case 512 * 512 * 128: x  = (const float*)d_in[i]; break;
            case 128 * 2048:      Wx = (const float*)d_in[i]; break;
            case 512 * 2048:      Wh = (const float*)d_in[i]; break;
            case 2048:            b  = (const float*)d_in[i]; break;
            case 512 * 128:       Wp = (const float*)d_in[i]; break;
            case 128:             bp = (const float*)d_in[i]; break;
            default: break;
        }
    }
    float* out = (float*)d_out;

    cudaFuncSetAttribute(lstm_rec, cudaFuncAttributeMaxDynamicSharedMemorySize, REC_SMEM);

    conv_w<<<512, 256>>>(Wx, Wh);
    conv_x<<<512, 256>>>(x);
    reset_k<<<128, 256>>>();
    lstm_rec<<<NCTA, 384, REC_SMEM>>>(b);
    proj_kernel<<<512, 128>>>(Wp, bp, out);
}